// round 2
// baseline (speedup 1.0000x reference)
#include <cuda_runtime.h>
#include <cstdint>

#define NA 8
#define NB 16384
#define NS 456
#define NACT 16
#define NIDIM 472
#define NH 256
#define NE 4
#define ND 64

// ---------------- scratch (device globals; no allocations allowed) ----------
__device__ float g_sa_enc[(size_t)NA * NB * NH];
__device__ float g_s_enc [(size_t)NA * NB * NH];
__device__ float g_keys  [(size_t)NA * NB * NH];
__device__ float g_vals  [(size_t)NA * NB * NH];
__device__ float g_sels  [(size_t)NA * NB * NH];
__device__ float g_other [(size_t)NA * NB * NH];
__device__ float g_h     [(size_t)NA * NB * NH];

// ---------------- generic tiled GEMM --------------------------------------
// Y[a, m, n] = act( sum_k X(a,m,k) * W(a,k,n) + bias(a,n) )
// X(a,m,k) = k < K0 ? X0[a*xs0 + m*K0 + k] : X1[a*xs1 + m*(K-K0) + (k-K0)]
// WL==0: W per agent, row-major [K][N], base W + a*ws
// WL==1: shared heads weight [E][H][64]: W[((n>>6)*NH + k)*64 + (n&63)]
#define BM 128
#define BN 64
#define BK 16

template<int WL, bool HAS_BIAS, bool ACT>
__global__ __launch_bounds__(256)
void gemm_k(const float* __restrict__ X0, const float* __restrict__ X1,
            int K0, int K,
            const float* __restrict__ W, const float* __restrict__ bias,
            float* __restrict__ Y,
            long xs0, long xs1, long ws, long bs, int N)
{
    const int a   = blockIdx.z;
    const int tid = threadIdx.x;
    const int tx  = tid & 15;         // 0..15 -> col group
    const int ty  = tid >> 4;         // 0..15 -> row group
    const int rowBase = blockIdx.y * BM;
    const int colBase = blockIdx.x * BN;

    const float* x0 = X0 + (long)a * xs0;
    const float* x1 = X1 ? (X1 + (long)a * xs1) : nullptr;
    const float* w  = (WL == 0) ? (W + (long)a * ws) : W;
    const int K1 = K - K0;

    __shared__ float As[BK][BM + 4];
    __shared__ float Ws[BK][BN];

    float acc[8][4];
#pragma unroll
    for (int i = 0; i < 8; i++)
#pragma unroll
        for (int j = 0; j < 4; j++) acc[i][j] = 0.f;

    for (int k0 = 0; k0 < K; k0 += BK) {
        // load A tile: BM x BK = 2048 elems, 8 per thread
#pragma unroll
        for (int l = 0; l < 8; l++) {
            int id = tid + l * 256;
            int r = id >> 4;          // row in tile (m)
            int c = id & 15;          // k within tile
            int k = k0 + c;
            float v = 0.f;
            if (k < K) {
                int m = rowBase + r;
                if (k < K0) v = __ldg(&x0[(long)m * K0 + k]);
                else        v = __ldg(&x1[(long)m * K1 + (k - K0)]);
            }
            As[c][r] = v;
        }
        // load W tile: BK x BN = 1024 elems, 4 per thread
#pragma unroll
        for (int l = 0; l < 4; l++) {
            int id = tid + l * 256;
            int r = id >> 6;          // k within tile
            int c = id & 63;          // n within tile
            int k = k0 + r;
            float v = 0.f;
            if (k < K) {
                int n = colBase + c;
                if (WL == 0) v = __ldg(&w[(long)k * N + n]);
                else         v = __ldg(&W[((long)(n >> 6) * NH + k) * 64 + (n & 63)]);
            }
            Ws[r][c] = v;
        }
        __syncthreads();

#pragma unroll
        for (int kk = 0; kk < BK; kk++) {
            float ar[8], br[4];
            *(float4*)&ar[0] = *(const float4*)&As[kk][ty * 8];
            *(float4*)&ar[4] = *(const float4*)&As[kk][ty * 8 + 4];
            *(float4*)&br[0] = *(const float4*)&Ws[kk][tx * 4];
#pragma unroll
            for (int i = 0; i < 8; i++)
#pragma unroll
                for (int j = 0; j < 4; j++)
                    acc[i][j] = fmaf(ar[i], br[j], acc[i][j]);
        }
        __syncthreads();
    }

    // epilogue
    const int row0 = rowBase + ty * 8;
    const int col0 = colBase + tx * 4;
    float b4[4] = {0.f, 0.f, 0.f, 0.f};
    if (HAS_BIAS) {
        const float* bp = bias + (long)a * bs + col0;
#pragma unroll
        for (int j = 0; j < 4; j++) b4[j] = __ldg(&bp[j]);
    }
    float* y = Y + ((long)a * NB + row0) * N + col0;
#pragma unroll
    for (int i = 0; i < 8; i++) {
        float4 o;
        float v0 = acc[i][0] + b4[0];
        float v1 = acc[i][1] + b4[1];
        float v2 = acc[i][2] + b4[2];
        float v3 = acc[i][3] + b4[3];
        if (ACT) {
            v0 = v0 > 0.f ? v0 : 0.01f * v0;
            v1 = v1 > 0.f ? v1 : 0.01f * v1;
            v2 = v2 > 0.f ? v2 : 0.01f * v2;
            v3 = v3 > 0.f ? v3 : 0.01f * v3;
        }
        o.x = v0; o.y = v1; o.z = v2; o.w = v3;
        *(float4*)(y + (long)i * N) = o;
    }
}

// ---------------- attention over agents ------------------------------------
__global__ __launch_bounds__(256)
void attn_k(const float* __restrict__ keys, const float* __restrict__ sels,
            const float* __restrict__ vals, float* __restrict__ other)
{
    const int b = blockIdx.x;
    __shared__ float sk[NA][NH + 1];
    __shared__ float ss[NA][NH + 1];
    __shared__ float sv[NA][NH + 1];
    __shared__ float lg[NE][NA][NA];
    __shared__ float pr[NE][NA][NA];

    const int tid = threadIdx.x;
    for (int i = tid; i < NA * NH; i += 256) {
        int ag = i >> 8;
        int h  = i & 255;
        long off = ((long)ag * NB + b) * NH + h;
        sk[ag][h] = keys[off];
        ss[ag][h] = sels[off];
        sv[ag][h] = vals[off];
    }
    __syncthreads();

    // logits: 256 threads -> (e,i,j)
    {
        int e = tid >> 6;
        int i = (tid >> 3) & 7;
        int j = tid & 7;
        const float* sp = &ss[i][e * ND];
        const float* kp = &sk[j][e * ND];
        float s = 0.f;
#pragma unroll
        for (int d = 0; d < ND; d++) s = fmaf(sp[d], kp[d], s);
        lg[e][i][j] = (i == j) ? -1e9f : s * 0.125f;   // 1/sqrt(64)
    }
    __syncthreads();

    // softmax: 32 threads -> (e,i)
    if (tid < NE * NA) {
        int e = tid >> 3;
        int i = tid & 7;
        float mx = -1e30f;
#pragma unroll
        for (int j = 0; j < NA; j++) mx = fmaxf(mx, lg[e][i][j]);
        float p[NA]; float sum = 0.f;
#pragma unroll
        for (int j = 0; j < NA; j++) { p[j] = expf(lg[e][i][j] - mx); sum += p[j]; }
        float inv = 1.f / sum;
#pragma unroll
        for (int j = 0; j < NA; j++) pr[e][i][j] = p[j] * inv;
    }
    __syncthreads();

    // other[i][b][e*64+d] = sum_j pr * vals
    for (int o = tid; o < NA * NH; o += 256) {
        int i = o >> 8;
        int h = o & 255;
        int e = h >> 6;
        float s = 0.f;
#pragma unroll
        for (int j = 0; j < NA; j++) s = fmaf(pr[e][i][j], sv[j][h], s);
        other[((long)i * NB + b) * NH + h] = s;
    }
}

// ---------------- final: argmax(actions) + q = h . c_W2[:,act] + b ---------
__global__ __launch_bounds__(256)
void q_k(const float* __restrict__ hbuf, const float* __restrict__ actions,
         const float* __restrict__ c_W2, const float* __restrict__ c_b2,
         float* __restrict__ q)
{
    const int gw = (blockIdx.x * blockDim.x + threadIdx.x) >> 5;
    const int lane = threadIdx.x & 31;
    if (gw >= NA * NB) return;
    const int a = gw >> 14;        // / 16384
    const int b = gw & (NB - 1);

    // warp argmax over 16 actions (first-max tie break)
    const float* ap = actions + ((long)a * NB + b) * NACT;
    float av = (lane < NACT) ? ap[lane] : -1e30f;
    int ai = lane;
#pragma unroll
    for (int off = 16; off > 0; off >>= 1) {
        float ov = __shfl_down_sync(0xFFFFFFFFu, av, off);
        int   oi = __shfl_down_sync(0xFFFFFFFFu, ai, off);
        if (ov > av || (ov == av && oi < ai)) { av = ov; ai = oi; }
    }
    ai = __shfl_sync(0xFFFFFFFFu, ai, 0);

    const float* hp = hbuf + ((long)a * NB + b) * NH;
    const float* wp = c_W2 + (long)a * NH * NACT + ai;
    float s = 0.f;
#pragma unroll
    for (int it = 0; it < NH / 32; it++) {
        int h = lane + it * 32;
        s = fmaf(hp[h], wp[(long)h * NACT], s);
    }
#pragma unroll
    for (int off = 16; off > 0; off >>= 1)
        s += __shfl_down_sync(0xFFFFFFFFu, s, off);
    if (lane == 0) q[gw] = s + c_b2[a * NACT + ai];
}

// ---------------- launcher --------------------------------------------------
extern "C" void kernel_launch(void* const* d_in, const int* in_sizes, int n_in,
                              void* d_out, int out_size)
{
    const float* states  = (const float*)d_in[0];
    const float* actions = (const float*)d_in[1];
    const float* enc_W   = (const float*)d_in[2];
    const float* enc_b   = (const float*)d_in[3];
    const float* s_W     = (const float*)d_in[4];
    const float* s_b     = (const float*)d_in[5];
    const float* key_W   = (const float*)d_in[6];
    const float* sel_W   = (const float*)d_in[7];
    const float* val_W   = (const float*)d_in[8];
    const float* val_b   = (const float*)d_in[9];
    const float* c_W1    = (const float*)d_in[10];
    const float* c_b1    = (const float*)d_in[11];
    const float* c_W2    = (const float*)d_in[12];
    const float* c_b2    = (const float*)d_in[13];
    float* q = (float*)d_out;

    float *sa_enc, *s_enc, *keys, *vals, *sels, *other, *hbuf;
    cudaGetSymbolAddress((void**)&sa_enc, g_sa_enc);
    cudaGetSymbolAddress((void**)&s_enc,  g_s_enc);
    cudaGetSymbolAddress((void**)&keys,   g_keys);
    cudaGetSymbolAddress((void**)&vals,   g_vals);
    cudaGetSymbolAddress((void**)&sels,   g_sels);
    cudaGetSymbolAddress((void**)&other,  g_other);
    cudaGetSymbolAddress((void**)&hbuf,   g_h);

    dim3 blk(256);
    dim3 g256(NH / BN, NB / BM, NA);   // (4, 128, 8)

    // 1) sa_enc = lrelu(concat(states,actions) @ enc_W + enc_b)
    gemm_k<0, true, true><<<g256, blk>>>(
        states, actions, NS, NIDIM, enc_W, enc_b, sa_enc,
        (long)NB * NS, (long)NB * NACT, (long)NIDIM * NH, NH, NH);

    // 2) s_enc = lrelu(states @ s_W + s_b)
    gemm_k<0, true, true><<<g256, blk>>>(
        states, nullptr, NS, NS, s_W, s_b, s_enc,
        (long)NB * NS, 0, (long)NS * NH, NH, NH);

    // 3) keys = sa_enc @ key_W      (heads layout, no bias/act)
    gemm_k<1, false, false><<<g256, blk>>>(
        sa_enc, nullptr, NH, NH, key_W, nullptr, keys,
        (long)NB * NH, 0, 0, 0, NH);

    // 4) vals = lrelu(sa_enc @ val_W + val_b)   (val_b shared across agents)
    gemm_k<1, true, true><<<g256, blk>>>(
        sa_enc, nullptr, NH, NH, val_W, val_b, vals,
        (long)NB * NH, 0, 0, 0, NH);

    // 5) sels = s_enc @ sel_W
    gemm_k<1, false, false><<<g256, blk>>>(
        s_enc, nullptr, NH, NH, sel_W, nullptr, sels,
        (long)NB * NH, 0, 0, 0, NH);

    // 6) attention across agents
    attn_k<<<NB, 256>>>(keys, sels, vals, other);

    // 7) h = lrelu(concat(s_enc, other) @ c_W1 + c_b1)
    gemm_k<0, true, true><<<g256, blk>>>(
        s_enc, other, NH, 2 * NH, c_W1, c_b1, hbuf,
        (long)NB * NH, (long)NB * NH, (long)(2 * NH) * NH, NH, NH);

    // 8) q = (h @ c_W2 + c_b2)[argmax(actions)]
    q_k<<<(NA * NB * 32) / 256, 256>>>(hbuf, actions, c_W2, c_b2, q);
}

// round 3
// speedup vs baseline: 2.2903x; 2.2903x over previous
#include <cuda_runtime.h>
#include <cstdint>

#define NA 8
#define NB 16384
#define NS 456
#define NACT 16
#define NIDIM 472
#define NH 256
#define NE 4
#define ND 64

// ---------------- scratch (device globals; no allocations allowed) ----------
__device__ float g_sa_enc[(size_t)NA * NB * NH];
__device__ float g_s_enc [(size_t)NA * NB * NH];
__device__ float g_keys  [(size_t)NA * NB * NH];
__device__ float g_vals  [(size_t)NA * NB * NH];
__device__ float g_sels  [(size_t)NA * NB * NH];
__device__ float g_other [(size_t)NA * NB * NH];
__device__ float g_h     [(size_t)NA * NB * NH];

// ---------------- cp.async helpers -----------------------------------------
__device__ __forceinline__ uint32_t s2u(const void* p) {
    uint32_t a;
    asm("{ .reg .u64 t; cvta.to.shared.u64 t, %1; cvt.u32.u64 %0, t; }"
        : "=r"(a) : "l"(p));
    return a;
}
#define CPA16(d, s) asm volatile("cp.async.ca.shared.global [%0], [%1], 16;" :: "r"(d), "l"(s))
#define CPA4(d, s)  asm volatile("cp.async.ca.shared.global [%0], [%1], 4;"  :: "r"(d), "l"(s))
#define CPC()  asm volatile("cp.async.commit_group;")
#define CPW0() asm volatile("cp.async.wait_group 0;")

// ---------------- double-buffered 128x128x8 SGEMM ---------------------------
// Y[a, m, n] = act( sum_k X(a,m,k) * W(a,k,n) + bias(a,n) )
// X(a,m,k) = k < K0 ? X0[a*xs0 + m*K0 + k] : X1[a*xs1 + m*(K-K0) + (k-K0)]
// WL==0: W per agent, row-major [K][N], base W + a*ws
// WL==1: shared heads weight [E][H][64]: W[((n>>6)*NH + k)*64 + (n&63)]
// Requirements baked in: M%128==0, N%128==0, K%8==0, K0%4==0. N==NH or 2*NH etc.
template<int WL, bool HAS_BIAS, bool ACT>
__global__ __launch_bounds__(256)
void gemm2(const float* __restrict__ X0, const float* __restrict__ X1,
           int K0, int K,
           const float* __restrict__ W, const float* __restrict__ bias,
           float* __restrict__ Y,
           long xs0, long xs1, long ws, long bs, int N)
{
    const int a   = blockIdx.z;
    const int tid = threadIdx.x;
    const int tx  = tid & 15;            // 16 col groups
    const int ty  = tid >> 4;            // 16 row groups
    const int rowBase = blockIdx.y * 128;
    const int colBase = blockIdx.x * 128;

    const float* x0 = X0 + (long)a * xs0;
    const float* x1 = X1 ? (X1 + (long)a * xs1) : nullptr;
    const float* w  = (WL == 0) ? (W + (long)a * ws) : W;
    const int K1 = K - K0;

    __shared__ float As[2][8][128];      // [buf][k][m]  (transposed A)
    __shared__ float Bs[2][8][128];      // [buf][k][n]

    // load mapping
    const int m_l = tid >> 1;            // 0..127 : A row
    const int hk  = (tid & 1) * 4;       // 0 or 4 : A k-offset (4 elems)
    const int kb  = tid >> 5;            // 0..7   : B k row
    const int cb  = (tid & 31) * 4;      // B col (float4)

    const uint32_t asA = s2u(&As[0][hk][m_l]);
    const uint32_t asB = s2u(&Bs[0][kb][cb]);
    const uint32_t bufBytes = 8 * 128 * 4;

    float acc[8][8];
#pragma unroll
    for (int i = 0; i < 8; i++)
#pragma unroll
        for (int j = 0; j < 8; j++) acc[i][j] = 0.f;

    auto issueLoads = [&](int buf, int kc) {
        // A tile: 4 x 4B cp.async per thread (transposed store)
        {
            int k = kc + hk;
            const float* src = (k < K0)
                ? x0 + (long)(rowBase + m_l) * K0 + k
                : x1 + (long)(rowBase + m_l) * (long)K1 + (k - K0);
            uint32_t d = asA + buf * bufBytes;
            CPA4(d,            src);
            CPA4(d + 128 * 4,  src + 1);
            CPA4(d + 256 * 4,  src + 2);
            CPA4(d + 384 * 4,  src + 3);
        }
        // B tile: 1 x 16B cp.async per thread
        {
            int k = kc + kb;
            int n = colBase + cb;
            const float* src = (WL == 0)
                ? w + (long)k * N + n
                : W + ((long)(n >> 6) * NH + k) * 64 + (n & 63);
            CPA16(asB + buf * bufBytes, src);
        }
    };

    const int nT = K >> 3;
    issueLoads(0, 0);
    CPC(); CPW0();
    __syncthreads();

    int buf = 0;
    for (int t = 0; t < nT; ++t) {
        if (t + 1 < nT) { issueLoads(buf ^ 1, (t + 1) * 8); CPC(); }

#pragma unroll
        for (int kk = 0; kk < 8; ++kk) {
            float4 a0 = *(const float4*)&As[buf][kk][ty * 4];
            float4 a1 = *(const float4*)&As[buf][kk][64 + ty * 4];
            float4 b0 = *(const float4*)&Bs[buf][kk][tx * 4];
            float4 b1 = *(const float4*)&Bs[buf][kk][64 + tx * 4];
            float av[8] = {a0.x, a0.y, a0.z, a0.w, a1.x, a1.y, a1.z, a1.w};
            float bv[8] = {b0.x, b0.y, b0.z, b0.w, b1.x, b1.y, b1.z, b1.w};
#pragma unroll
            for (int r = 0; r < 8; r++)
#pragma unroll
                for (int c = 0; c < 8; c++)
                    acc[r][c] = fmaf(av[r], bv[c], acc[r][c]);
        }

        CPW0();
        __syncthreads();
        buf ^= 1;
    }

    // epilogue
    float bcol[8] = {0.f, 0.f, 0.f, 0.f, 0.f, 0.f, 0.f, 0.f};
    if (HAS_BIAS) {
        const float* bp = bias + (long)a * bs + colBase;
#pragma unroll
        for (int j = 0; j < 4; j++) bcol[j]     = bp[tx * 4 + j];
#pragma unroll
        for (int j = 0; j < 4; j++) bcol[4 + j] = bp[64 + tx * 4 + j];
    }

    float* yb = Y + ((long)a * NB + rowBase) * N + colBase;
#pragma unroll
    for (int half = 0; half < 2; half++) {
#pragma unroll
        for (int r = 0; r < 4; r++) {
            int row = half * 64 + ty * 4 + r;
            float* yr = yb + (long)row * N;
            float v[8];
#pragma unroll
            for (int c = 0; c < 8; c++) {
                float t = acc[half * 4 + r][c] + bcol[c];
                if (ACT) t = t > 0.f ? t : 0.01f * t;
                v[c] = t;
            }
            float4 o0 = {v[0], v[1], v[2], v[3]};
            float4 o1 = {v[4], v[5], v[6], v[7]};
            *(float4*)(yr + tx * 4)      = o0;
            *(float4*)(yr + 64 + tx * 4) = o1;
        }
    }
}

// ---------------- attention over agents ------------------------------------
__global__ __launch_bounds__(256)
void attn_k(const float* __restrict__ keys, const float* __restrict__ sels,
            const float* __restrict__ vals, float* __restrict__ other)
{
    const int b = blockIdx.x;
    __shared__ float sk[NA][NH + 1];
    __shared__ float ss[NA][NH + 1];
    __shared__ float sv[NA][NH + 1];
    __shared__ float lg[NE][NA][NA];
    __shared__ float pr[NE][NA][NA];

    const int tid = threadIdx.x;
    for (int i = tid; i < NA * NH; i += 256) {
        int ag = i >> 8;
        int h  = i & 255;
        long off = ((long)ag * NB + b) * NH + h;
        sk[ag][h] = keys[off];
        ss[ag][h] = sels[off];
        sv[ag][h] = vals[off];
    }
    __syncthreads();

    // logits: 256 threads -> (e,i,j)
    {
        int e = tid >> 6;
        int i = (tid >> 3) & 7;
        int j = tid & 7;
        const float* sp = &ss[i][e * ND];
        const float* kp = &sk[j][e * ND];
        float s = 0.f;
#pragma unroll
        for (int d = 0; d < ND; d++) s = fmaf(sp[d], kp[d], s);
        lg[e][i][j] = (i == j) ? -1e9f : s * 0.125f;   // 1/sqrt(64)
    }
    __syncthreads();

    // softmax: 32 threads -> (e,i)
    if (tid < NE * NA) {
        int e = tid >> 3;
        int i = tid & 7;
        float mx = -1e30f;
#pragma unroll
        for (int j = 0; j < NA; j++) mx = fmaxf(mx, lg[e][i][j]);
        float p[NA]; float sum = 0.f;
#pragma unroll
        for (int j = 0; j < NA; j++) { p[j] = expf(lg[e][i][j] - mx); sum += p[j]; }
        float inv = 1.f / sum;
#pragma unroll
        for (int j = 0; j < NA; j++) pr[e][i][j] = p[j] * inv;
    }
    __syncthreads();

    // other[i][b][e*64+d] = sum_j pr * vals
    for (int o = tid; o < NA * NH; o += 256) {
        int i = o >> 8;
        int h = o & 255;
        int e = h >> 6;
        float s = 0.f;
#pragma unroll
        for (int j = 0; j < NA; j++) s = fmaf(pr[e][i][j], sv[j][h], s);
        other[((long)i * NB + b) * NH + h] = s;
    }
}

// ---------------- final: argmax(actions) + q = h . c_W2[:,act] + b ---------
__global__ __launch_bounds__(256)
void q_k(const float* __restrict__ hbuf, const float* __restrict__ actions,
         const float* __restrict__ c_W2, const float* __restrict__ c_b2,
         float* __restrict__ q)
{
    const int gw = (blockIdx.x * blockDim.x + threadIdx.x) >> 5;
    const int lane = threadIdx.x & 31;
    if (gw >= NA * NB) return;
    const int a = gw >> 14;        // / 16384
    const int b = gw & (NB - 1);

    // warp argmax over 16 actions (first-max tie break)
    const float* ap = actions + ((long)a * NB + b) * NACT;
    float av = (lane < NACT) ? ap[lane] : -1e30f;
    int ai = lane;
#pragma unroll
    for (int off = 16; off > 0; off >>= 1) {
        float ov = __shfl_down_sync(0xFFFFFFFFu, av, off);
        int   oi = __shfl_down_sync(0xFFFFFFFFu, ai, off);
        if (ov > av || (ov == av && oi < ai)) { av = ov; ai = oi; }
    }
    ai = __shfl_sync(0xFFFFFFFFu, ai, 0);

    const float* hp = hbuf + ((long)a * NB + b) * NH;
    const float* wp = c_W2 + (long)a * NH * NACT + ai;
    float s = 0.f;
#pragma unroll
    for (int it = 0; it < NH / 32; it++) {
        int h = lane + it * 32;
        s = fmaf(hp[h], wp[(long)h * NACT], s);
    }
#pragma unroll
    for (int off = 16; off > 0; off >>= 1)
        s += __shfl_down_sync(0xFFFFFFFFu, s, off);
    if (lane == 0) q[gw] = s + c_b2[a * NACT + ai];
}

// ---------------- launcher --------------------------------------------------
extern "C" void kernel_launch(void* const* d_in, const int* in_sizes, int n_in,
                              void* d_out, int out_size)
{
    const float* states  = (const float*)d_in[0];
    const float* actions = (const float*)d_in[1];
    const float* enc_W   = (const float*)d_in[2];
    const float* enc_b   = (const float*)d_in[3];
    const float* s_W     = (const float*)d_in[4];
    const float* s_b     = (const float*)d_in[5];
    const float* key_W   = (const float*)d_in[6];
    const float* sel_W   = (const float*)d_in[7];
    const float* val_W   = (const float*)d_in[8];
    const float* val_b   = (const float*)d_in[9];
    const float* c_W1    = (const float*)d_in[10];
    const float* c_b1    = (const float*)d_in[11];
    const float* c_W2    = (const float*)d_in[12];
    const float* c_b2    = (const float*)d_in[13];
    float* q = (float*)d_out;

    float *sa_enc, *s_enc, *keys, *vals, *sels, *other, *hbuf;
    cudaGetSymbolAddress((void**)&sa_enc, g_sa_enc);
    cudaGetSymbolAddress((void**)&s_enc,  g_s_enc);
    cudaGetSymbolAddress((void**)&keys,   g_keys);
    cudaGetSymbolAddress((void**)&vals,   g_vals);
    cudaGetSymbolAddress((void**)&sels,   g_sels);
    cudaGetSymbolAddress((void**)&other,  g_other);
    cudaGetSymbolAddress((void**)&hbuf,   g_h);

    dim3 blk(256);
    dim3 grd(NH / 128, NB / 128, NA);    // (2, 128, 8)

    // 1) sa_enc = lrelu(concat(states,actions) @ enc_W + enc_b)
    gemm2<0, true, true><<<grd, blk>>>(
        states, actions, NS, NIDIM, enc_W, enc_b, sa_enc,
        (long)NB * NS, (long)NB * NACT, (long)NIDIM * NH, NH, NH);

    // 2) s_enc = lrelu(states @ s_W + s_b)
    gemm2<0, true, true><<<grd, blk>>>(
        states, nullptr, NS, NS, s_W, s_b, s_enc,
        (long)NB * NS, 0, (long)NS * NH, NH, NH);

    // 3) keys = sa_enc @ key_W      (heads layout, no bias/act)
    gemm2<1, false, false><<<grd, blk>>>(
        sa_enc, nullptr, NH, NH, key_W, nullptr, keys,
        (long)NB * NH, 0, 0, 0, NH);

    // 4) vals = lrelu(sa_enc @ val_W + val_b)   (val_b shared across agents)
    gemm2<1, true, true><<<grd, blk>>>(
        sa_enc, nullptr, NH, NH, val_W, val_b, vals,
        (long)NB * NH, 0, 0, 0, NH);

    // 5) sels = s_enc @ sel_W
    gemm2<1, false, false><<<grd, blk>>>(
        s_enc, nullptr, NH, NH, sel_W, nullptr, sels,
        (long)NB * NH, 0, 0, 0, NH);

    // 6) attention across agents
    attn_k<<<NB, 256>>>(keys, sels, vals, other);

    // 7) h = lrelu(concat(s_enc, other) @ c_W1 + c_b1)
    gemm2<0, true, true><<<grd, blk>>>(
        s_enc, other, NH, 2 * NH, c_W1, c_b1, hbuf,
        (long)NB * NH, (long)NB * NH, (long)(2 * NH) * NH, NH, NH);

    // 8) q = (h @ c_W2 + c_b2)[argmax(actions)]
    q_k<<<(NA * NB * 32) / 256, 256>>>(hbuf, actions, c_W2, c_b2, q);
}

// round 5
// speedup vs baseline: 3.4675x; 1.5140x over previous
#include <cuda_runtime.h>
#include <cstdint>

#define NA 8
#define NB 16384
#define NS 456
#define NACT 16
#define NIDIM 472
#define NH 256
#define NE 4
#define ND 64

// ---------------- scratch (device globals; no allocations allowed) ----------
__device__ float g_sa_enc[(size_t)NA * NB * NH];
__device__ float g_s_enc [(size_t)NA * NB * NH];
__device__ float g_keys  [(size_t)NA * NB * NH];
__device__ float g_vals  [(size_t)NA * NB * NH];
__device__ float g_sels  [(size_t)NA * NB * NH];
__device__ float g_other [(size_t)NA * NB * NH];
__device__ float g_h     [(size_t)NA * NB * NH];

// transposed weights: [A][N=256][Kpad]
__device__ float g_wt_enc[(size_t)NA * 256 * 480];
__device__ float g_wt_s  [(size_t)NA * 256 * 480];
__device__ float g_wt_c1 [(size_t)NA * 256 * 512];
__device__ float g_wt_key[(size_t)256 * 256];
__device__ float g_wt_sel[(size_t)256 * 256];
__device__ float g_wt_val[(size_t)256 * 256];

// ---------------- helpers ----------------------------------------------------
__device__ __forceinline__ uint32_t s2u(const void* p) {
    uint32_t a;
    asm("{ .reg .u64 t; cvta.to.shared.u64 t, %1; cvt.u32.u64 %0, t; }"
        : "=r"(a) : "l"(p));
    return a;
}
#define CPA16Z(d, s, sz) \
    asm volatile("cp.async.cg.shared.global [%0], [%1], 16, %2;" \
                 :: "r"(d), "l"(s), "r"(sz))
#define CPA16(d, s) \
    asm volatile("cp.async.cg.shared.global [%0], [%1], 16;" :: "r"(d), "l"(s))
#define CPC()  asm volatile("cp.async.commit_group;")
#define CPW0() asm volatile("cp.async.wait_group 0;")

// split x = hi + lo; hi has 19-bit mantissa (exact tf32), lo = remainder.
__device__ __forceinline__ void split_tf32(float x, uint32_t& hi, uint32_t& lo) {
    uint32_t u = __float_as_uint(x) & 0xffffe000u;
    hi = u;
    lo = __float_as_uint(x - __uint_as_float(u));
}

#define MMA_TF32(d, a, b0, b1) \
    asm volatile("mma.sync.aligned.m16n8k8.row.col.f32.tf32.tf32.f32 " \
        "{%0,%1,%2,%3}, {%4,%5,%6,%7}, {%8,%9}, {%0,%1,%2,%3};" \
        : "+f"((d)[0]), "+f"((d)[1]), "+f"((d)[2]), "+f"((d)[3]) \
        : "r"((a)[0]), "r"((a)[1]), "r"((a)[2]), "r"((a)[3]), "r"(b0), "r"(b1))

// ---------------- prep kernels: transpose to [N][Kpad] ----------------------
__global__ void prep_w_k(const float* __restrict__ W, float* __restrict__ WT,
                         int K, int Kpad, int total)
{
    int i = blockIdx.x * 256 + threadIdx.x;
    if (i >= total) return;
    int kp = i % Kpad;
    int n  = (i / Kpad) & 255;
    int a  = i / (Kpad * 256);
    WT[i] = (kp < K) ? W[((long)a * K + kp) * 256 + n] : 0.f;
}
__global__ void prep_h_k(const float* __restrict__ W, float* __restrict__ WT)
{
    int i = blockIdx.x * 256 + threadIdx.x;   // 65536
    int k = i & 255;
    int n = i >> 8;
    WT[(long)n * 256 + k] = W[((long)(n >> 6) * 256 + k) * 64 + (n & 63)];
}

// ---------------- 3xTF32 mma.sync GEMM: 128x128 CTA tile --------------------
// Y[a, m, n] = act( X(a,m,:) @ W + bias[n] ), N = 256 total (2 CTAs in x).
// X(a,m,k) = k<K0 ? X0[a][m][k] : X1[a][m][k-K0].  WT: [a][256][Kpad] (k-major).
#define TSTR  40                      // smem row stride in floats (160B)
#define TILE_B (128 * TSTR * 4)       // 20480 bytes per tile buffer
#define SMEM_TOT (4 * TILE_B)         // A(x2 buf) + B(x2 buf) = 81920

__global__ __launch_bounds__(256, 2)
void gemmM(const float* __restrict__ X0, const float* __restrict__ X1,
           int K0, int K, int Kpad,
           const float* __restrict__ WT, long wstride,
           const float* __restrict__ bias, long bstride, int act,
           float* __restrict__ Y, long xs0, long xs1)
{
    extern __shared__ char smem[];
    const uint32_t sbA = s2u(smem);
    const uint32_t sbB = sbA + 2 * TILE_B;
    float* fA = (float*)smem;
    float* fB = (float*)(smem + 2 * TILE_B);

    const int a = blockIdx.z;
    const int tid = threadIdx.x;
    const int lane = tid & 31;
    const int wid = tid >> 5;
    const int wm = wid & 3;           // 4 warps over M
    const int wn = wid >> 2;          // 2 warps over N
    const int lr = lane >> 2;
    const int lc = lane & 3;
    const int rowBase = blockIdx.y * 128;
    const int colBase = blockIdx.x * 128;

    const float* pX0 = X0 + (long)a * xs0;
    const float* pX1 = X1 ? (X1 + (long)a * xs1) : X0;
    const float* pW  = WT + (long)a * wstride;
    const int K1 = K - K0;

    float acc[2][8][4];
#pragma unroll
    for (int mt = 0; mt < 2; mt++)
#pragma unroll
        for (int nt = 0; nt < 8; nt++)
#pragma unroll
            for (int j = 0; j < 4; j++) acc[mt][nt][j] = 0.f;

    const int jj = tid & 7;           // 16B column group within 32-k chunk
    const int r0 = tid >> 3;          // base row (0..31), +32 per t

    auto issueStage = [&](int buf, int c) {
        const int kc = c * 32;
        const int k = kc + jj * 4;
        // ---- A (activations, bounds + concat via zfill) ----
        const bool v0 = (k < K0);
        const bool v1 = (k < K);
        const uint32_t sz = v1 ? 16u : 0u;
#pragma unroll
        for (int t = 0; t < 4; t++) {
            const int r = r0 + t * 32;
            const float* s = v0 ? (pX0 + (long)(rowBase + r) * K0 + k)
                                : (v1 ? (pX1 + (long)(rowBase + r) * (long)K1 + (k - K0))
                                      : pX0);
            CPA16Z(sbA + buf * TILE_B + (uint32_t)((r * TSTR + jj * 4) * 4), s, sz);
        }
        // ---- B (pre-transposed weights, always in range: Kpad padded) ----
#pragma unroll
        for (int t = 0; t < 4; t++) {
            const int n = r0 + t * 32;
            const float* s = pW + (long)(colBase + n) * Kpad + k;
            CPA16(sbB + buf * TILE_B + (uint32_t)((n * TSTR + jj * 4) * 4), s);
        }
    };

    const int nst = Kpad >> 5;
    issueStage(0, 0); CPC();

    for (int c = 0; c < nst; c++) {
        const int buf = c & 1;
        CPW0();
        __syncthreads();
        if (c + 1 < nst) { issueStage(buf ^ 1, c + 1); CPC(); }

        const float* sA = fA + buf * (128 * TSTR);
        const float* sB = fB + buf * (128 * TSTR);

#pragma unroll
        for (int kk = 0; kk < 4; kk++) {
            const int k = kk * 8;
            uint32_t ah[2][4], al[2][4];
#pragma unroll
            for (int mt = 0; mt < 2; mt++) {
                const int m0 = wm * 32 + mt * 16 + lr;
                float x0 = sA[(m0)     * TSTR + k + lc];
                float x1 = sA[(m0 + 8) * TSTR + k + lc];
                float x2 = sA[(m0)     * TSTR + k + 4 + lc];
                float x3 = sA[(m0 + 8) * TSTR + k + 4 + lc];
                split_tf32(x0, ah[mt][0], al[mt][0]);
                split_tf32(x1, ah[mt][1], al[mt][1]);
                split_tf32(x2, ah[mt][2], al[mt][2]);
                split_tf32(x3, ah[mt][3], al[mt][3]);
            }
#pragma unroll
            for (int nt = 0; nt < 8; nt++) {
                const int n0 = wn * 64 + nt * 8 + lr;
                float y0 = sB[n0 * TSTR + k + lc];
                float y1 = sB[n0 * TSTR + k + 4 + lc];
                uint32_t bh0, bl0, bh1, bl1;
                split_tf32(y0, bh0, bl0);
                split_tf32(y1, bh1, bl1);
#pragma unroll
                for (int mt = 0; mt < 2; mt++) {
                    MMA_TF32(acc[mt][nt], ah[mt], bh0, bh1);
                    MMA_TF32(acc[mt][nt], al[mt], bh0, bh1);
                    MMA_TF32(acc[mt][nt], ah[mt], bl0, bl1);
                }
            }
        }
    }

    // ---- epilogue: bias + leaky relu, float2 stores ------------------------
#pragma unroll
    for (int mt = 0; mt < 2; mt++) {
        const int row = rowBase + wm * 32 + mt * 16 + lr;
#pragma unroll
        for (int nt = 0; nt < 8; nt++) {
            const int gcol = colBase + wn * 64 + nt * 8 + lc * 2;
            float b0 = 0.f, b1 = 0.f;
            if (bias) {
                b0 = bias[(long)a * bstride + gcol];
                b1 = bias[(long)a * bstride + gcol + 1];
            }
            float v0 = acc[mt][nt][0] + b0;
            float v1 = acc[mt][nt][1] + b1;
            float v2 = acc[mt][nt][2] + b0;
            float v3 = acc[mt][nt][3] + b1;
            if (act) {
                v0 = v0 > 0.f ? v0 : 0.01f * v0;
                v1 = v1 > 0.f ? v1 : 0.01f * v1;
                v2 = v2 > 0.f ? v2 : 0.01f * v2;
                v3 = v3 > 0.f ? v3 : 0.01f * v3;
            }
            float2 o0 = {v0, v1};
            float2 o1 = {v2, v3};
            *(float2*)(Y + ((long)a * NB + row) * NH + gcol)       = o0;
            *(float2*)(Y + ((long)a * NB + row + 8) * NH + gcol)   = o1;
        }
    }
}

// ---------------- attention over agents ------------------------------------
__global__ __launch_bounds__(256)
void attn_k(const float* __restrict__ keys, const float* __restrict__ sels,
            const float* __restrict__ vals, float* __restrict__ other)
{
    const int b = blockIdx.x;
    __shared__ float sk[NA][NH + 1];
    __shared__ float ss[NA][NH + 1];
    __shared__ float sv[NA][NH + 1];
    __shared__ float lg[NE][NA][NA];
    __shared__ float pr[NE][NA][NA];

    const int tid = threadIdx.x;
    for (int i = tid; i < NA * NH; i += 256) {
        int ag = i >> 8;
        int h  = i & 255;
        long off = ((long)ag * NB + b) * NH + h;
        sk[ag][h] = keys[off];
        ss[ag][h] = sels[off];
        sv[ag][h] = vals[off];
    }
    __syncthreads();

    {
        int e = tid >> 6;
        int i = (tid >> 3) & 7;
        int j = tid & 7;
        const float* sp = &ss[i][e * ND];
        const float* kp = &sk[j][e * ND];
        float s = 0.f;
#pragma unroll
        for (int d = 0; d < ND; d++) s = fmaf(sp[d], kp[d], s);
        lg[e][i][j] = (i == j) ? -1e9f : s * 0.125f;
    }
    __syncthreads();

    if (tid < NE * NA) {
        int e = tid >> 3;
        int i = tid & 7;
        float mx = -1e30f;
#pragma unroll
        for (int j = 0; j < NA; j++) mx = fmaxf(mx, lg[e][i][j]);
        float p[NA]; float sum = 0.f;
#pragma unroll
        for (int j = 0; j < NA; j++) { p[j] = expf(lg[e][i][j] - mx); sum += p[j]; }
        float inv = 1.f / sum;
#pragma unroll
        for (int j = 0; j < NA; j++) pr[e][i][j] = p[j] * inv;
    }
    __syncthreads();

    for (int o = tid; o < NA * NH; o += 256) {
        int i = o >> 8;
        int h = o & 255;
        int e = h >> 6;
        float s = 0.f;
#pragma unroll
        for (int j = 0; j < NA; j++) s = fmaf(pr[e][i][j], sv[j][h], s);
        other[((long)i * NB + b) * NH + h] = s;
    }
}

// ---------------- final: argmax(actions) + q = h . c_W2[:,act] + b ---------
__global__ __launch_bounds__(256)
void q_k(const float* __restrict__ hbuf, const float* __restrict__ actions,
         const float* __restrict__ c_W2, const float* __restrict__ c_b2,
         float* __restrict__ q)
{
    const int gw = (blockIdx.x * blockDim.x + threadIdx.x) >> 5;
    const int lane = threadIdx.x & 31;
    if (gw >= NA * NB) return;
    const int a = gw >> 14;
    const int b = gw & (NB - 1);

    const float* ap = actions + ((long)a * NB + b) * NACT;
    float av = (lane < NACT) ? ap[lane] : -1e30f;
    int ai = lane;
#pragma unroll
    for (int off = 16; off > 0; off >>= 1) {
        float ov = __shfl_down_sync(0xFFFFFFFFu, av, off);
        int   oi = __shfl_down_sync(0xFFFFFFFFu, ai, off);
        if (ov > av || (ov == av && oi < ai)) { av = ov; ai = oi; }
    }
    ai = __shfl_sync(0xFFFFFFFFu, ai, 0);

    const float* hp = hbuf + ((long)a * NB + b) * NH;
    const float* wp = c_W2 + (long)a * NH * NACT + ai;
    float s = 0.f;
#pragma unroll
    for (int it = 0; it < NH / 32; it++) {
        int h = lane + it * 32;
        s = fmaf(hp[h], wp[(long)h * NACT], s);
    }
#pragma unroll
    for (int off = 16; off > 0; off >>= 1)
        s += __shfl_down_sync(0xFFFFFFFFu, s, off);
    if (lane == 0) q[gw] = s + c_b2[a * NACT + ai];
}

// ---------------- launcher --------------------------------------------------
extern "C" void kernel_launch(void* const* d_in, const int* in_sizes, int n_in,
                              void* d_out, int out_size)
{
    const float* states  = (const float*)d_in[0];
    const float* actions = (const float*)d_in[1];
    const float* enc_W   = (const float*)d_in[2];
    const float* enc_b   = (const float*)d_in[3];
    const float* s_W     = (const float*)d_in[4];
    const float* s_b     = (const float*)d_in[5];
    const float* key_W   = (const float*)d_in[6];
    const float* sel_W   = (const float*)d_in[7];
    const float* val_W   = (const float*)d_in[8];
    const float* val_b   = (const float*)d_in[9];
    const float* c_W1    = (const float*)d_in[10];
    const float* c_b1    = (const float*)d_in[11];
    const float* c_W2    = (const float*)d_in[12];
    const float* c_b2    = (const float*)d_in[13];
    float* q = (float*)d_out;

    float *sa_enc, *s_enc, *keys, *vals, *sels, *other, *hbuf;
    cudaGetSymbolAddress((void**)&sa_enc, g_sa_enc);
    cudaGetSymbolAddress((void**)&s_enc,  g_s_enc);
    cudaGetSymbolAddress((void**)&keys,   g_keys);
    cudaGetSymbolAddress((void**)&vals,   g_vals);
    cudaGetSymbolAddress((void**)&sels,   g_sels);
    cudaGetSymbolAddress((void**)&other,  g_other);
    cudaGetSymbolAddress((void**)&hbuf,   g_h);

    float *wtE, *wtS, *wtC, *wtK, *wtQ, *wtV;
    cudaGetSymbolAddress((void**)&wtE, g_wt_enc);
    cudaGetSymbolAddress((void**)&wtS, g_wt_s);
    cudaGetSymbolAddress((void**)&wtC, g_wt_c1);
    cudaGetSymbolAddress((void**)&wtK, g_wt_key);
    cudaGetSymbolAddress((void**)&wtQ, g_wt_sel);
    cudaGetSymbolAddress((void**)&wtV, g_wt_val);

    cudaFuncSetAttribute(gemmM, cudaFuncAttributeMaxDynamicSharedMemorySize, SMEM_TOT);

    // ---- prep: transpose weights ------------------------------------------
    {
        int tE = NA * 256 * 480;
        prep_w_k<<<(tE + 255) / 256, 256>>>(enc_W, wtE, NIDIM, 480, tE);
        prep_w_k<<<(tE + 255) / 256, 256>>>(s_W,   wtS, NS,    480, tE);
        int tC = NA * 256 * 512;
        prep_w_k<<<(tC + 255) / 256, 256>>>(c_W1,  wtC, 512,   512, tC);
        prep_h_k<<<256, 256>>>(key_W, wtK);
        prep_h_k<<<256, 256>>>(sel_W, wtQ);
        prep_h_k<<<256, 256>>>(val_W, wtV);
    }

    dim3 blk(256);
    dim3 grd(2, NB / 128, NA);   // (n-tiles, m-tiles, agents)

    // 1) sa_enc = lrelu(concat(states,actions) @ enc_W + enc_b)
    gemmM<<<grd, blk, SMEM_TOT>>>(states, actions, NS, NIDIM, 480,
        wtE, (long)256 * 480, enc_b, NH, 1, sa_enc,
        (long)NB * NS, (long)NB * NACT);

    // 2) s_enc = lrelu(states @ s_W + s_b)
    gemmM<<<grd, blk, SMEM_TOT>>>(states, nullptr, NS, NS, 480,
        wtS, (long)256 * 480, s_b, NH, 1, s_enc,
        (long)NB * NS, 0);

    // 3) keys = sa_enc @ key_W
    gemmM<<<grd, blk, SMEM_TOT>>>(sa_enc, nullptr, NH, NH, 256,
        wtK, 0, nullptr, 0, 0, keys, (long)NB * NH, 0);

    // 4) vals = lrelu(sa_enc @ val_W + val_b)
    gemmM<<<grd, blk, SMEM_TOT>>>(sa_enc, nullptr, NH, NH, 256,
        wtV, 0, val_b, 0, 1, vals, (long)NB * NH, 0);

    // 5) sels = s_enc @ sel_W
    gemmM<<<grd, blk, SMEM_TOT>>>(s_enc, nullptr, NH, NH, 256,
        wtQ, 0, nullptr, 0, 0, sels, (long)NB * NH, 0);

    // 6) attention across agents
    attn_k<<<NB, 256>>>(keys, sels, vals, other);

    // 7) h = lrelu(concat(s_enc, other) @ c_W1 + c_b1)
    gemmM<<<grd, blk, SMEM_TOT>>>(s_enc, other, NH, 2 * NH, 512,
        wtC, (long)256 * 512, c_b1, NH, 1, hbuf,
        (long)NB * NH, (long)NB * NH);

    // 8) q = (h @ c_W2 + c_b2)[argmax(actions)]
    q_k<<<(NA * NB * 32) / 256, 256>>>(hbuf, actions, c_W2, c_b2, q);
}

// round 6
// speedup vs baseline: 4.6309x; 1.3355x over previous
#include <cuda_runtime.h>
#include <cuda_fp16.h>
#include <cstdint>

#define NA 8
#define NB 16384
#define NS 456
#define NACT 16
#define NIDIM 472
#define NH 256
#define NE 4
#define ND 64

#define KP_IN  480     // padded K for enc / s_enc GEMMs
#define KP_H   256     // K for head GEMMs
#define KP_C   512     // K for critic GEMM

// ---------------- scratch (device globals; no allocations allowed) ----------
// half-pair activation buffers
__device__ __half g_xin_h[(size_t)NA * NB * KP_IN];
__device__ __half g_xin_l[(size_t)NA * NB * KP_IN];
__device__ __half g_sa_h [(size_t)NA * NB * NH];
__device__ __half g_sa_l [(size_t)NA * NB * NH];
__device__ __half g_ci_h [(size_t)NA * NB * KP_C];   // [s_enc | other]
__device__ __half g_ci_l [(size_t)NA * NB * KP_C];
// fp32 buffers
__device__ float g_keys[(size_t)NA * NB * NH];
__device__ float g_vals[(size_t)NA * NB * NH];
__device__ float g_sels[(size_t)NA * NB * NH];
__device__ float g_h   [(size_t)NA * NB * NH];
// transposed split weights: [A][N=256][Kpad] halves
__device__ __half g_wE_h[(size_t)NA * 256 * KP_IN];
__device__ __half g_wE_l[(size_t)NA * 256 * KP_IN];
__device__ __half g_wS_h[(size_t)NA * 256 * KP_IN];
__device__ __half g_wS_l[(size_t)NA * 256 * KP_IN];
__device__ __half g_wC_h[(size_t)NA * 256 * KP_C];
__device__ __half g_wC_l[(size_t)NA * 256 * KP_C];
__device__ __half g_wK_h[(size_t)256 * 256];
__device__ __half g_wK_l[(size_t)256 * 256];
__device__ __half g_wQ_h[(size_t)256 * 256];
__device__ __half g_wQ_l[(size_t)256 * 256];
__device__ __half g_wV_h[(size_t)256 * 256];
__device__ __half g_wV_l[(size_t)256 * 256];

// ---------------- helpers ----------------------------------------------------
__device__ __forceinline__ uint32_t s2u(const void* p) {
    uint32_t a;
    asm("{ .reg .u64 t; cvta.to.shared.u64 t, %1; cvt.u32.u64 %0, t; }"
        : "=r"(a) : "l"(p));
    return a;
}
#define CPA16(d, s) \
    asm volatile("cp.async.cg.shared.global [%0], [%1], 16;" :: "r"(d), "l"(s))
#define CPC()  asm volatile("cp.async.commit_group;")
#define CPW0() asm volatile("cp.async.wait_group 0;")

__device__ __forceinline__ void split_h(float x, __half& hi, __half& lo) {
    hi = __float2half_rn(x);
    lo = __float2half_rn(x - __half2float(hi));
}

#define MMA_F16(d, a, b0, b1) \
    asm volatile("mma.sync.aligned.m16n8k16.row.col.f32.f16.f16.f32 " \
        "{%0,%1,%2,%3}, {%4,%5,%6,%7}, {%8,%9}, {%0,%1,%2,%3};" \
        : "+f"((d)[0]), "+f"((d)[1]), "+f"((d)[2]), "+f"((d)[3]) \
        : "r"((a)[0]), "r"((a)[1]), "r"((a)[2]), "r"((a)[3]), "r"(b0), "r"(b1))

// ---------------- prep kernels ----------------------------------------------
// xin = [states | actions | 0pad] -> split halves, [A][B][480]
__global__ void prep_x(const float* __restrict__ st, const float* __restrict__ ac,
                       __half* __restrict__ xh, __half* __restrict__ xl)
{
    long i = (long)blockIdx.x * 256 + threadIdx.x;
    if (i >= (long)NA * NB * KP_IN) return;
    int kp = (int)(i % KP_IN);
    long ab = i / KP_IN;               // a*NB + b
    float v = 0.f;
    if (kp < NS)          v = st[ab * NS + kp];
    else if (kp < NIDIM)  v = ac[ab * NACT + (kp - NS)];
    __half h, l; split_h(v, h, l);
    xh[i] = h; xl[i] = l;
}
// W [a][K][256] -> [a][256][Kpad] split halves
__global__ void prep_w(const float* __restrict__ W, __half* __restrict__ wh,
                       __half* __restrict__ wl, int K, int Kpad, long total)
{
    long i = (long)blockIdx.x * 256 + threadIdx.x;
    if (i >= total) return;
    int kp = (int)(i % Kpad);
    int n  = (int)((i / Kpad) & 255);
    int a  = (int)(i / ((long)Kpad * 256));
    float v = (kp < K) ? W[((long)a * K + kp) * 256 + n] : 0.f;
    __half h, l; split_h(v, h, l);
    wh[i] = h; wl[i] = l;
}
// heads W [4][256][64] -> [256][256] split halves (n = e*64+d)
__global__ void prep_h(const float* __restrict__ W, __half* __restrict__ wh,
                       __half* __restrict__ wl)
{
    int i = blockIdx.x * 256 + threadIdx.x;   // 65536
    int k = i & 255;
    int n = i >> 8;
    float v = W[((long)(n >> 6) * 256 + k) * 64 + (n & 63)];
    __half h, l; split_h(v, h, l);
    wh[(long)n * 256 + k] = h;
    wl[(long)n * 256 + k] = l;
}

// ---------------- fp16 split-16 GEMM: 128x128 CTA tile ----------------------
// Y[a,m,n] = act( X(a,m,:) @ W + bias[n] ), total N=256 (2 CTAs in x).
// A: half-pair [a][astride per row], dense K = Kpad.  B: [a?][256][Kpad].
#define TS 40                         // smem row stride in halves (80B)
#define BUFB (128 * TS * 2)           // 10240 bytes per buffer
#define OFF_AH 0
#define OFF_AL (2 * BUFB)
#define OFF_BH (4 * BUFB)
#define OFF_BL (6 * BUFB)
#define SMEM_TOT (8 * BUFB)           // 81920

__global__ __launch_bounds__(256, 2)
void gemmH(const __half* __restrict__ Ah, const __half* __restrict__ Al,
           int astride, int Kpad,
           const __half* __restrict__ Bh, const __half* __restrict__ Bl,
           long wstride, const float* __restrict__ bias, long bstride, int act,
           float* __restrict__ Yf, __half* __restrict__ Yh, __half* __restrict__ Yl,
           int ostr)
{
    extern __shared__ char smem[];
    const uint32_t sb = s2u(smem);

    const int a = blockIdx.z;
    const int tid = threadIdx.x;
    const int lane = tid & 31;
    const int wid = tid >> 5;
    const int wm = wid & 3;
    const int wn = wid >> 2;
    const int lr = lane >> 2;
    const int lc = lane & 3;
    const int rowBase = blockIdx.y * 128;
    const int colBase = blockIdx.x * 128;

    const __half* pAh = Ah + (long)a * NB * astride + (long)rowBase * astride;
    const __half* pAl = Al + (long)a * NB * astride + (long)rowBase * astride;
    const __half* pBh = Bh + (long)a * wstride + (long)colBase * Kpad;
    const __half* pBl = Bl + (long)a * wstride + (long)colBase * Kpad;

    float acc[2][8][4];
#pragma unroll
    for (int mt = 0; mt < 2; mt++)
#pragma unroll
        for (int nt = 0; nt < 8; nt++)
#pragma unroll
            for (int j = 0; j < 4; j++) acc[mt][nt][j] = 0.f;

    const int rrow = tid >> 2;        // 0..63 per pass (2 passes of 64? no: 256/4=64... )
    const int grp  = tid & 3;         // 16B group within 32-half row

    auto issueStage = [&](int buf, int kc) {
#pragma unroll
        for (int t = 0; t < 2; t++) {
            const int row = rrow + t * 64;
            const uint32_t dst = (uint32_t)(row * (TS * 2) + grp * 16);
            const long  aoff = (long)row * astride + kc + grp * 8;
            const long  boff = (long)row * Kpad    + kc + grp * 8;
            CPA16(sb + OFF_AH + buf * BUFB + dst, pAh + aoff);
            CPA16(sb + OFF_AL + buf * BUFB + dst, pAl + aoff);
            CPA16(sb + OFF_BH + buf * BUFB + dst, pBh + boff);
            CPA16(sb + OFF_BL + buf * BUFB + dst, pBl + boff);
        }
    };

    const int nst = Kpad >> 5;
    issueStage(0, 0); CPC();

    for (int c = 0; c < nst; c++) {
        const int buf = c & 1;
        CPW0();
        __syncthreads();
        if (c + 1 < nst) { issueStage(buf ^ 1, (c + 1) * 32); CPC(); }

        const __half* sAh = (const __half*)(smem + OFF_AH + buf * BUFB);
        const __half* sAl = (const __half*)(smem + OFF_AL + buf * BUFB);
        const __half* sBh = (const __half*)(smem + OFF_BH + buf * BUFB);
        const __half* sBl = (const __half*)(smem + OFF_BL + buf * BUFB);

#pragma unroll
        for (int kk = 0; kk < 2; kk++) {
            const int kb = kk * 16 + 2 * lc;
            uint32_t ah[2][4], al[2][4];
#pragma unroll
            for (int mt = 0; mt < 2; mt++) {
                const int o = (wm * 32 + mt * 16 + lr) * TS + kb;
                ah[mt][0] = *(const uint32_t*)&sAh[o];
                ah[mt][1] = *(const uint32_t*)&sAh[o + 8 * TS];
                ah[mt][2] = *(const uint32_t*)&sAh[o + 8];
                ah[mt][3] = *(const uint32_t*)&sAh[o + 8 * TS + 8];
                al[mt][0] = *(const uint32_t*)&sAl[o];
                al[mt][1] = *(const uint32_t*)&sAl[o + 8 * TS];
                al[mt][2] = *(const uint32_t*)&sAl[o + 8];
                al[mt][3] = *(const uint32_t*)&sAl[o + 8 * TS + 8];
            }
#pragma unroll
            for (int nt = 0; nt < 8; nt++) {
                const int o = (wn * 64 + nt * 8 + lr) * TS + kb;
                uint32_t bh0 = *(const uint32_t*)&sBh[o];
                uint32_t bh1 = *(const uint32_t*)&sBh[o + 8];
                uint32_t bl0 = *(const uint32_t*)&sBl[o];
                uint32_t bl1 = *(const uint32_t*)&sBl[o + 8];
#pragma unroll
                for (int mt = 0; mt < 2; mt++) {
                    MMA_F16(acc[mt][nt], ah[mt], bh0, bh1);
                    MMA_F16(acc[mt][nt], al[mt], bh0, bh1);
                    MMA_F16(acc[mt][nt], ah[mt], bl0, bl1);
                }
            }
        }
        __syncthreads();
    }

    // ---- epilogue ----------------------------------------------------------
#pragma unroll
    for (int mt = 0; mt < 2; mt++) {
        const int row = rowBase + wm * 32 + mt * 16 + lr;
#pragma unroll
        for (int nt = 0; nt < 8; nt++) {
            const int gcol = colBase + wn * 64 + nt * 8 + lc * 2;
            float b0 = 0.f, b1 = 0.f;
            if (bias) {
                b0 = bias[(long)a * bstride + gcol];
                b1 = bias[(long)a * bstride + gcol + 1];
            }
            float v0 = acc[mt][nt][0] + b0;
            float v1 = acc[mt][nt][1] + b1;
            float v2 = acc[mt][nt][2] + b0;
            float v3 = acc[mt][nt][3] + b1;
            if (act) {
                v0 = v0 > 0.f ? v0 : 0.01f * v0;
                v1 = v1 > 0.f ? v1 : 0.01f * v1;
                v2 = v2 > 0.f ? v2 : 0.01f * v2;
                v3 = v3 > 0.f ? v3 : 0.01f * v3;
            }
            if (Yf) {
                float2 o0 = {v0, v1};
                float2 o1 = {v2, v3};
                *(float2*)(Yf + ((long)a * NB + row) * NH + gcol)     = o0;
                *(float2*)(Yf + ((long)a * NB + row + 8) * NH + gcol) = o1;
            } else {
                __half h0, l0, h1, l1, h2, l2, h3, l3;
                split_h(v0, h0, l0); split_h(v1, h1, l1);
                split_h(v2, h2, l2); split_h(v3, h3, l3);
                long i0 = ((long)a * NB + row) * ostr + gcol;
                long i1 = ((long)a * NB + row + 8) * ostr + gcol;
                *(__half2*)(Yh + i0) = __halves2half2(h0, h1);
                *(__half2*)(Yl + i0) = __halves2half2(l0, l1);
                *(__half2*)(Yh + i1) = __halves2half2(h2, h3);
                *(__half2*)(Yl + i1) = __halves2half2(l2, l3);
            }
        }
    }
}

// ---------------- attention over agents ------------------------------------
__global__ __launch_bounds__(256)
void attn_k(const float* __restrict__ keys, const float* __restrict__ sels,
            const float* __restrict__ vals,
            __half* __restrict__ ci_h, __half* __restrict__ ci_l)
{
    const int b = blockIdx.x;
    __shared__ float sk[NA][NH + 1];
    __shared__ float ss[NA][NH + 1];
    __shared__ float sv[NA][NH + 1];
    __shared__ float lg[NE][NA][NA];
    __shared__ float pr[NE][NA][NA];

    const int tid = threadIdx.x;
    for (int i = tid; i < NA * NH; i += 256) {
        int ag = i >> 8;
        int h  = i & 255;
        long off = ((long)ag * NB + b) * NH + h;
        sk[ag][h] = keys[off];
        ss[ag][h] = sels[off];
        sv[ag][h] = vals[off];
    }
    __syncthreads();

    {
        int e = tid >> 6;
        int i = (tid >> 3) & 7;
        int j = tid & 7;
        const float* sp = &ss[i][e * ND];
        const float* kp = &sk[j][e * ND];
        float s = 0.f;
#pragma unroll
        for (int d = 0; d < ND; d++) s = fmaf(sp[d], kp[d], s);
        lg[e][i][j] = (i == j) ? -1e9f : s * 0.125f;
    }
    __syncthreads();

    if (tid < NE * NA) {
        int e = tid >> 3;
        int i = tid & 7;
        float mx = -1e30f;
#pragma unroll
        for (int j = 0; j < NA; j++) mx = fmaxf(mx, lg[e][i][j]);
        float p[NA]; float sum = 0.f;
#pragma unroll
        for (int j = 0; j < NA; j++) { p[j] = expf(lg[e][i][j] - mx); sum += p[j]; }
        float inv = 1.f / sum;
#pragma unroll
        for (int j = 0; j < NA; j++) pr[e][i][j] = p[j] * inv;
    }
    __syncthreads();

    for (int o = tid; o < NA * NH; o += 256) {
        int i = o >> 8;
        int h = o & 255;
        int e = h >> 6;
        float s = 0.f;
#pragma unroll
        for (int j = 0; j < NA; j++) s = fmaf(pr[e][i][j], sv[j][h], s);
        __half hv, lv; split_h(s, hv, lv);
        long idx = ((long)i * NB + b) * KP_C + NH + h;
        ci_h[idx] = hv;
        ci_l[idx] = lv;
    }
}

// ---------------- final: argmax(actions) + q = h . c_W2[:,act] + b ---------
__global__ __launch_bounds__(256)
void q_k(const float* __restrict__ hbuf, const float* __restrict__ actions,
         const float* __restrict__ c_W2, const float* __restrict__ c_b2,
         float* __restrict__ q)
{
    const int gw = (blockIdx.x * blockDim.x + threadIdx.x) >> 5;
    const int lane = threadIdx.x & 31;
    if (gw >= NA * NB) return;
    const int a = gw >> 14;
    const int b = gw & (NB - 1);

    const float* ap = actions + ((long)a * NB + b) * NACT;
    float av = (lane < NACT) ? ap[lane] : -1e30f;
    int ai = lane;
#pragma unroll
    for (int off = 16; off > 0; off >>= 1) {
        float ov = __shfl_down_sync(0xFFFFFFFFu, av, off);
        int   oi = __shfl_down_sync(0xFFFFFFFFu, ai, off);
        if (ov > av || (ov == av && oi < ai)) { av = ov; ai = oi; }
    }
    ai = __shfl_sync(0xFFFFFFFFu, ai, 0);

    const float* hp = hbuf + ((long)a * NB + b) * NH;
    const float* wp = c_W2 + (long)a * NH * NACT + ai;
    float s = 0.f;
#pragma unroll
    for (int it = 0; it < NH / 32; it++) {
        int h = lane + it * 32;
        s = fmaf(hp[h], wp[(long)h * NACT], s);
    }
#pragma unroll
    for (int off = 16; off > 0; off >>= 1)
        s += __shfl_down_sync(0xFFFFFFFFu, s, off);
    if (lane == 0) q[gw] = s + c_b2[a * NACT + ai];
}

// ---------------- launcher --------------------------------------------------
extern "C" void kernel_launch(void* const* d_in, const int* in_sizes, int n_in,
                              void* d_out, int out_size)
{
    const float* states  = (const float*)d_in[0];
    const float* actions = (const float*)d_in[1];
    const float* enc_W   = (const float*)d_in[2];
    const float* enc_b   = (const float*)d_in[3];
    const float* s_W     = (const float*)d_in[4];
    const float* s_b     = (const float*)d_in[5];
    const float* key_W   = (const float*)d_in[6];
    const float* sel_W   = (const float*)d_in[7];
    const float* val_W   = (const float*)d_in[8];
    const float* val_b   = (const float*)d_in[9];
    const float* c_W1    = (const float*)d_in[10];
    const float* c_b1    = (const float*)d_in[11];
    const float* c_W2    = (const float*)d_in[12];
    const float* c_b2    = (const float*)d_in[13];
    float* q = (float*)d_out;

    __half *xh, *xl, *sah, *sal, *cih, *cil;
    cudaGetSymbolAddress((void**)&xh,  g_xin_h);
    cudaGetSymbolAddress((void**)&xl,  g_xin_l);
    cudaGetSymbolAddress((void**)&sah, g_sa_h);
    cudaGetSymbolAddress((void**)&sal, g_sa_l);
    cudaGetSymbolAddress((void**)&cih, g_ci_h);
    cudaGetSymbolAddress((void**)&cil, g_ci_l);
    float *keys, *vals, *sels, *hbuf;
    cudaGetSymbolAddress((void**)&keys, g_keys);
    cudaGetSymbolAddress((void**)&vals, g_vals);
    cudaGetSymbolAddress((void**)&sels, g_sels);
    cudaGetSymbolAddress((void**)&hbuf, g_h);
    __half *wEh, *wEl, *wSh, *wSl, *wCh, *wCl, *wKh, *wKl, *wQh, *wQl, *wVh, *wVl;
    cudaGetSymbolAddress((void**)&wEh, g_wE_h);
    cudaGetSymbolAddress((void**)&wEl, g_wE_l);
    cudaGetSymbolAddress((void**)&wSh, g_wS_h);
    cudaGetSymbolAddress((void**)&wSl, g_wS_l);
    cudaGetSymbolAddress((void**)&wCh, g_wC_h);
    cudaGetSymbolAddress((void**)&wCl, g_wC_l);
    cudaGetSymbolAddress((void**)&wKh, g_wK_h);
    cudaGetSymbolAddress((void**)&wKl, g_wK_l);
    cudaGetSymbolAddress((void**)&wQh, g_wQ_h);
    cudaGetSymbolAddress((void**)&wQl, g_wQ_l);
    cudaGetSymbolAddress((void**)&wVh, g_wV_h);
    cudaGetSymbolAddress((void**)&wVl, g_wV_l);

    cudaFuncSetAttribute(gemmH, cudaFuncAttributeMaxDynamicSharedMemorySize, SMEM_TOT);

    // ---- prep ---------------------------------------------------------------
    {
        long tX = (long)NA * NB * KP_IN;
        prep_x<<<(unsigned)((tX + 255) / 256), 256>>>(states, actions, xh, xl);
        long tE = (long)NA * 256 * KP_IN;
        prep_w<<<(unsigned)((tE + 255) / 256), 256>>>(enc_W, wEh, wEl, NIDIM, KP_IN, tE);
        prep_w<<<(unsigned)((tE + 255) / 256), 256>>>(s_W,   wSh, wSl, NS,    KP_IN, tE);
        long tC = (long)NA * 256 * KP_C;
        prep_w<<<(unsigned)((tC + 255) / 256), 256>>>(c_W1,  wCh, wCl, KP_C,  KP_C,  tC);
        prep_h<<<256, 256>>>(key_W, wKh, wKl);
        prep_h<<<256, 256>>>(sel_W, wQh, wQl);
        prep_h<<<256, 256>>>(val_W, wVh, wVl);
    }

    dim3 blk(256);
    dim3 grd(2, NB / 128, NA);

    // 1) sa_enc (half-pair out)
    gemmH<<<grd, blk, SMEM_TOT>>>(xh, xl, KP_IN, KP_IN, wEh, wEl,
        (long)256 * KP_IN, enc_b, NH, 1, nullptr, sah, sal, NH);

    // 2) s_enc -> ci cols [0,256)
    gemmH<<<grd, blk, SMEM_TOT>>>(xh, xl, KP_IN, KP_IN, wSh, wSl,
        (long)256 * KP_IN, s_b, NH, 1, nullptr, cih, cil, KP_C);

    // 3) keys (fp32)
    gemmH<<<grd, blk, SMEM_TOT>>>(sah, sal, NH, KP_H, wKh, wKl,
        0, nullptr, 0, 0, keys, nullptr, nullptr, 0);

    // 4) vals (fp32, shared bias)
    gemmH<<<grd, blk, SMEM_TOT>>>(sah, sal, NH, KP_H, wVh, wVl,
        0, val_b, 0, 1, vals, nullptr, nullptr, 0);

    // 5) sels (fp32) — A = s_enc living in ci (row stride 512)
    gemmH<<<grd, blk, SMEM_TOT>>>(cih, cil, KP_C, KP_H, wQh, wQl,
        0, nullptr, 0, 0, sels, nullptr, nullptr, 0);

    // 6) attention -> ci cols [256,512)
    attn_k<<<NB, 256>>>(keys, sels, vals, cih, cil);

    // 7) h = lrelu(ci @ c_W1 + c_b1)  (fp32)
    gemmH<<<grd, blk, SMEM_TOT>>>(cih, cil, KP_C, KP_C, wCh, wCl,
        (long)256 * KP_C, c_b1, NH, 1, hbuf, nullptr, nullptr, 0);

    // 8) q
    q_k<<<(NA * NB * 32) / 256, 256>>>(hbuf, actions, c_W2, c_b2, q);
}

// round 7
// speedup vs baseline: 4.8941x; 1.0568x over previous
#include <cuda_runtime.h>
#include <cuda_fp16.h>
#include <cstdint>

#define NA 8
#define NB 16384
#define NS 456
#define NACT 16
#define NIDIM 472
#define NH 256
#define NE 4
#define ND 64

#define KP_IN  480
#define KP_H   256
#define KP_C   512

// ---------------- scratch (device globals) ----------------------------------
__device__ __half g_xin_h[(size_t)NA * NB * KP_IN];
__device__ __half g_xin_l[(size_t)NA * NB * KP_IN];
__device__ __half g_sa_h [(size_t)NA * NB * NH];
__device__ __half g_sa_l [(size_t)NA * NB * NH];
__device__ __half g_ci_h [(size_t)NA * NB * KP_C];   // [s_enc | other]
__device__ __half g_ci_l [(size_t)NA * NB * KP_C];
__device__ float g_keys[(size_t)NA * NB * NH];
__device__ float g_vals[(size_t)NA * NB * NH];
__device__ float g_sels[(size_t)NA * NB * NH];
__device__ float g_h   [(size_t)NA * NB * NH];
__device__ __half g_wE_h[(size_t)NA * 256 * KP_IN];
__device__ __half g_wE_l[(size_t)NA * 256 * KP_IN];
__device__ __half g_wS_h[(size_t)NA * 256 * KP_IN];
__device__ __half g_wS_l[(size_t)NA * 256 * KP_IN];
__device__ __half g_wC_h[(size_t)NA * 256 * KP_C];
__device__ __half g_wC_l[(size_t)NA * 256 * KP_C];
__device__ __half g_wKV_h[(size_t)512 * 256];       // [keys | vals] rows
__device__ __half g_wKV_l[(size_t)512 * 256];
__device__ __half g_wQ_h[(size_t)256 * 256];
__device__ __half g_wQ_l[(size_t)256 * 256];
__device__ float g_bias_kv[512];

// ---------------- helpers ----------------------------------------------------
__device__ __forceinline__ uint32_t s2u(const void* p) {
    uint32_t a;
    asm("{ .reg .u64 t; cvta.to.shared.u64 t, %1; cvt.u32.u64 %0, t; }"
        : "=r"(a) : "l"(p));
    return a;
}
#define CPA16(d, s) \
    asm volatile("cp.async.cg.shared.global [%0], [%1], 16;" :: "r"(d), "l"(s))
#define CPC()  asm volatile("cp.async.commit_group;")
#define CPW0() asm volatile("cp.async.wait_group 0;")
#define LDSM4(R0, R1, R2, R3, A) \
    asm volatile("ldmatrix.sync.aligned.m8n8.x4.shared.b16 {%0,%1,%2,%3}, [%4];" \
        : "=r"(R0), "=r"(R1), "=r"(R2), "=r"(R3) : "r"(A))

__device__ __forceinline__ void split_h(float x, __half& hi, __half& lo) {
    hi = __float2half_rn(x);
    lo = __float2half_rn(x - __half2float(hi));
}

#define MMA_F16(d, a, b0, b1) \
    asm volatile("mma.sync.aligned.m16n8k16.row.col.f32.f16.f16.f32 " \
        "{%0,%1,%2,%3}, {%4,%5,%6,%7}, {%8,%9}, {%0,%1,%2,%3};" \
        : "+f"((d)[0]), "+f"((d)[1]), "+f"((d)[2]), "+f"((d)[3]) \
        : "r"((a)[0]), "r"((a)[1]), "r"((a)[2]), "r"((a)[3]), "r"(b0), "r"(b1))

// ---------------- prep kernels ----------------------------------------------
__global__ void prep_x(const float* __restrict__ st, const float* __restrict__ ac,
                       __half* __restrict__ xh, __half* __restrict__ xl)
{
    long i = (long)blockIdx.x * 256 + threadIdx.x;
    if (i >= (long)NA * NB * KP_IN) return;
    int kp = (int)(i % KP_IN);
    long ab = i / KP_IN;
    float v = 0.f;
    if (kp < NS)          v = st[ab * NS + kp];
    else if (kp < NIDIM)  v = ac[ab * NACT + (kp - NS)];
    __half h, l; split_h(v, h, l);
    xh[i] = h; xl[i] = l;
}
__global__ void prep_w(const float* __restrict__ W, __half* __restrict__ wh,
                       __half* __restrict__ wl, int K, int Kpad, long total)
{
    long i = (long)blockIdx.x * 256 + threadIdx.x;
    if (i >= total) return;
    int kp = (int)(i % Kpad);
    int n  = (int)((i / Kpad) & 255);
    int a  = (int)(i / ((long)Kpad * 256));
    float v = (kp < K) ? W[((long)a * K + kp) * 256 + n] : 0.f;
    __half h, l; split_h(v, h, l);
    wh[i] = h; wl[i] = l;
}
__global__ void prep_h(const float* __restrict__ W, __half* __restrict__ wh,
                       __half* __restrict__ wl)
{
    int i = blockIdx.x * 256 + threadIdx.x;   // 65536
    int k = i & 255;
    int n = i >> 8;
    float v = W[((long)(n >> 6) * 256 + k) * 64 + (n & 63)];
    __half h, l; split_h(v, h, l);
    wh[(long)n * 256 + k] = h;
    wl[(long)n * 256 + k] = l;
}
__global__ void prep_bkv(const float* __restrict__ val_b, float* __restrict__ bkv)
{
    int i = threadIdx.x;   // 512
    bkv[i] = (i < 256) ? 0.f : val_b[i - 256];
}

// ---------------- fp16 split-16 GEMM, ldmatrix fragments --------------------
#define TS 40
#define BUFB (128 * TS * 2)
#define OFF_AH 0
#define OFF_AL (2 * BUFB)
#define OFF_BH (4 * BUFB)
#define OFF_BL (6 * BUFB)
#define SMEM_TOT (8 * BUFB)

__global__ __launch_bounds__(256, 2)
void gemmH(const __half* __restrict__ Ah, const __half* __restrict__ Al,
           int astride, int Kpad,
           const __half* __restrict__ Bh, const __half* __restrict__ Bl,
           long wstride, const float* __restrict__ bias, long bstride, int act,
           float* __restrict__ Yf, float* __restrict__ Yf2,
           __half* __restrict__ Yh, __half* __restrict__ Yl, int ostr)
{
    extern __shared__ char smem[];
    const uint32_t sb = s2u(smem);

    const int a = blockIdx.z;
    const int tid = threadIdx.x;
    const int lane = tid & 31;
    const int wid = tid >> 5;
    const int wm = wid & 3;
    const int wn = wid >> 2;
    const int lr = lane >> 2;
    const int lc = lane & 3;
    const int rowBase = blockIdx.y * 128;
    const int colBase = blockIdx.x * 128;

    const __half* pAh = Ah + (long)a * NB * astride + (long)rowBase * astride;
    const __half* pAl = Al + (long)a * NB * astride + (long)rowBase * astride;
    const __half* pBh = Bh + (long)a * wstride + (long)colBase * Kpad;
    const __half* pBl = Bl + (long)a * wstride + (long)colBase * Kpad;

    float acc[2][8][4];
#pragma unroll
    for (int mt = 0; mt < 2; mt++)
#pragma unroll
        for (int nt = 0; nt < 8; nt++)
#pragma unroll
            for (int j = 0; j < 4; j++) acc[mt][nt][j] = 0.f;

    // cp.async mapping
    const int rrow = tid >> 2;
    const int grp  = tid & 3;

    auto issueStage = [&](int buf, int kc) {
#pragma unroll
        for (int t = 0; t < 2; t++) {
            const int row = rrow + t * 64;
            const uint32_t dst = (uint32_t)(row * (TS * 2) + grp * 16);
            const long aoff = (long)row * astride + kc + grp * 8;
            const long boff = (long)row * Kpad    + kc + grp * 8;
            CPA16(sb + OFF_AH + buf * BUFB + dst, pAh + aoff);
            CPA16(sb + OFF_AL + buf * BUFB + dst, pAl + aoff);
            CPA16(sb + OFF_BH + buf * BUFB + dst, pBh + boff);
            CPA16(sb + OFF_BL + buf * BUFB + dst, pBl + boff);
        }
    };

    // ldmatrix per-lane byte offsets (within a buffer)
    const uint32_t aOff = (uint32_t)(((wm * 32 + (lane & 15)) * TS + (lane >> 4) * 8) * 2);
    const uint32_t bOff = (uint32_t)(((wn * 64 + (lane & 7) + ((lane >= 16) ? 8 : 0)) * TS
                                     + ((lane >> 3) & 1) * 8) * 2);

    const int nst = Kpad >> 5;
    issueStage(0, 0); CPC();

    for (int c = 0; c < nst; c++) {
        const int buf = c & 1;
        CPW0();
        __syncthreads();
        if (c + 1 < nst) { issueStage(buf ^ 1, (c + 1) * 32); CPC(); }

        const uint32_t sAh = sb + OFF_AH + buf * BUFB;
        const uint32_t sAl = sb + OFF_AL + buf * BUFB;
        const uint32_t sBh = sb + OFF_BH + buf * BUFB;
        const uint32_t sBl = sb + OFF_BL + buf * BUFB;

#pragma unroll
        for (int kk = 0; kk < 2; kk++) {
            const uint32_t kbB = kk * 32;           // 16 halves = 32 bytes
            uint32_t ah[2][4], al[2][4];
#pragma unroll
            for (int mt = 0; mt < 2; mt++) {
                const uint32_t ao = aOff + (uint32_t)(mt * 16 * TS * 2) + kbB;
                LDSM4(ah[mt][0], ah[mt][1], ah[mt][2], ah[mt][3], sAh + ao);
                LDSM4(al[mt][0], al[mt][1], al[mt][2], al[mt][3], sAl + ao);
            }
#pragma unroll
            for (int p = 0; p < 4; p++) {
                const uint32_t bo = bOff + (uint32_t)(p * 16 * TS * 2) + kbB;
                uint32_t bh[4], bl[4];
                LDSM4(bh[0], bh[1], bh[2], bh[3], sBh + bo);
                LDSM4(bl[0], bl[1], bl[2], bl[3], sBl + bo);
#pragma unroll
                for (int mt = 0; mt < 2; mt++) {
                    MMA_F16(acc[mt][2 * p],     ah[mt], bh[0], bh[1]);
                    MMA_F16(acc[mt][2 * p],     al[mt], bh[0], bh[1]);
                    MMA_F16(acc[mt][2 * p],     ah[mt], bl[0], bl[1]);
                    MMA_F16(acc[mt][2 * p + 1], ah[mt], bh[2], bh[3]);
                    MMA_F16(acc[mt][2 * p + 1], al[mt], bh[2], bh[3]);
                    MMA_F16(acc[mt][2 * p + 1], ah[mt], bl[2], bl[3]);
                }
            }
        }
        __syncthreads();
    }

    // ---- epilogue ----------------------------------------------------------
    const bool doAct = (act == 1) || (act == 2 && colBase >= 256);
#pragma unroll
    for (int mt = 0; mt < 2; mt++) {
        const int row = rowBase + wm * 32 + mt * 16 + lr;
#pragma unroll
        for (int nt = 0; nt < 8; nt++) {
            const int gcol = colBase + wn * 64 + nt * 8 + lc * 2;
            float b0 = 0.f, b1 = 0.f;
            if (bias) {
                b0 = bias[(long)a * bstride + gcol];
                b1 = bias[(long)a * bstride + gcol + 1];
            }
            float v0 = acc[mt][nt][0] + b0;
            float v1 = acc[mt][nt][1] + b1;
            float v2 = acc[mt][nt][2] + b0;
            float v3 = acc[mt][nt][3] + b1;
            if (doAct) {
                v0 = v0 > 0.f ? v0 : 0.01f * v0;
                v1 = v1 > 0.f ? v1 : 0.01f * v1;
                v2 = v2 > 0.f ? v2 : 0.01f * v2;
                v3 = v3 > 0.f ? v3 : 0.01f * v3;
            }
            if (Yf) {
                float* Yo = (Yf2 && gcol >= 256) ? Yf2 : Yf;
                const int oc = gcol & 255;
                float2 o0 = {v0, v1};
                float2 o1 = {v2, v3};
                *(float2*)(Yo + ((long)a * NB + row) * NH + oc)     = o0;
                *(float2*)(Yo + ((long)a * NB + row + 8) * NH + oc) = o1;
            } else {
                __half h0, l0, h1, l1, h2, l2, h3, l3;
                split_h(v0, h0, l0); split_h(v1, h1, l1);
                split_h(v2, h2, l2); split_h(v3, h3, l3);
                long i0 = ((long)a * NB + row) * ostr + gcol;
                long i1 = ((long)a * NB + row + 8) * ostr + gcol;
                *(__half2*)(Yh + i0) = __halves2half2(h0, h1);
                *(__half2*)(Yl + i0) = __halves2half2(l0, l1);
                *(__half2*)(Yh + i1) = __halves2half2(h2, h3);
                *(__half2*)(Yl + i1) = __halves2half2(l2, l3);
            }
        }
    }
}

// ---------------- attention over agents ------------------------------------
__global__ __launch_bounds__(256)
void attn_k(const float* __restrict__ keys, const float* __restrict__ sels,
            const float* __restrict__ vals,
            __half* __restrict__ ci_h, __half* __restrict__ ci_l)
{
    const int b = blockIdx.x;
    __shared__ float sk[NA][NH + 1];
    __shared__ float ss[NA][NH + 1];
    __shared__ float sv[NA][NH + 1];
    __shared__ float lg[NE][NA][NA];
    __shared__ float pr[NE][NA][NA];

    const int tid = threadIdx.x;
    for (int i = tid; i < NA * NH; i += 256) {
        int ag = i >> 8;
        int h  = i & 255;
        long off = ((long)ag * NB + b) * NH + h;
        sk[ag][h] = keys[off];
        ss[ag][h] = sels[off];
        sv[ag][h] = vals[off];
    }
    __syncthreads();

    {
        int e = tid >> 6;
        int i = (tid >> 3) & 7;
        int j = tid & 7;
        const float* sp = &ss[i][e * ND];
        const float* kp = &sk[j][e * ND];
        float s = 0.f;
#pragma unroll
        for (int d = 0; d < ND; d++) s = fmaf(sp[d], kp[d], s);
        lg[e][i][j] = (i == j) ? -1e9f : s * 0.125f;
    }
    __syncthreads();

    if (tid < NE * NA) {
        int e = tid >> 3;
        int i = tid & 7;
        float mx = -1e30f;
#pragma unroll
        for (int j = 0; j < NA; j++) mx = fmaxf(mx, lg[e][i][j]);
        float p[NA]; float sum = 0.f;
#pragma unroll
        for (int j = 0; j < NA; j++) { p[j] = expf(lg[e][i][j] - mx); sum += p[j]; }
        float inv = 1.f / sum;
#pragma unroll
        for (int j = 0; j < NA; j++) pr[e][i][j] = p[j] * inv;
    }
    __syncthreads();

    for (int o = tid; o < NA * NH; o += 256) {
        int i = o >> 8;
        int h = o & 255;
        int e = h >> 6;
        float s = 0.f;
#pragma unroll
        for (int j = 0; j < NA; j++) s = fmaf(pr[e][i][j], sv[j][h], s);
        __half hv, lv; split_h(s, hv, lv);
        long idx = ((long)i * NB + b) * KP_C + NH + h;
        ci_h[idx] = hv;
        ci_l[idx] = lv;
    }
}

// ---------------- final: argmax(actions) + q -------------------------------
__global__ __launch_bounds__(256)
void q_k(const float* __restrict__ hbuf, const float* __restrict__ actions,
         const float* __restrict__ c_W2, const float* __restrict__ c_b2,
         float* __restrict__ q)
{
    const int gw = (blockIdx.x * blockDim.x + threadIdx.x) >> 5;
    const int lane = threadIdx.x & 31;
    if (gw >= NA * NB) return;
    const int a = gw >> 14;
    const int b = gw & (NB - 1);

    const float* ap = actions + ((long)a * NB + b) * NACT;
    float av = (lane < NACT) ? ap[lane] : -1e30f;
    int ai = lane;
#pragma unroll
    for (int off = 16; off > 0; off >>= 1) {
        float ov = __shfl_down_sync(0xFFFFFFFFu, av, off);
        int   oi = __shfl_down_sync(0xFFFFFFFFu, ai, off);
        if (ov > av || (ov == av && oi < ai)) { av = ov; ai = oi; }
    }
    ai = __shfl_sync(0xFFFFFFFFu, ai, 0);

    const float* hp = hbuf + ((long)a * NB + b) * NH;
    const float* wp = c_W2 + (long)a * NH * NACT + ai;
    float s = 0.f;
#pragma unroll
    for (int it = 0; it < NH / 32; it++) {
        int h = lane + it * 32;
        s = fmaf(hp[h], wp[(long)h * NACT], s);
    }
#pragma unroll
    for (int off = 16; off > 0; off >>= 1)
        s += __shfl_down_sync(0xFFFFFFFFu, s, off);
    if (lane == 0) q[gw] = s + c_b2[a * NACT + ai];
}

// ---------------- launcher --------------------------------------------------
extern "C" void kernel_launch(void* const* d_in, const int* in_sizes, int n_in,
                              void* d_out, int out_size)
{
    const float* states  = (const float*)d_in[0];
    const float* actions = (const float*)d_in[1];
    const float* enc_W   = (const float*)d_in[2];
    const float* enc_b   = (const float*)d_in[3];
    const float* s_W     = (const float*)d_in[4];
    const float* s_b     = (const float*)d_in[5];
    const float* key_W   = (const float*)d_in[6];
    const float* sel_W   = (const float*)d_in[7];
    const float* val_W   = (const float*)d_in[8];
    const float* val_b   = (const float*)d_in[9];
    const float* c_W1    = (const float*)d_in[10];
    const float* c_b1    = (const float*)d_in[11];
    const float* c_W2    = (const float*)d_in[12];
    const float* c_b2    = (const float*)d_in[13];
    float* q = (float*)d_out;

    __half *xh, *xl, *sah, *sal, *cih, *cil;
    cudaGetSymbolAddress((void**)&xh,  g_xin_h);
    cudaGetSymbolAddress((void**)&xl,  g_xin_l);
    cudaGetSymbolAddress((void**)&sah, g_sa_h);
    cudaGetSymbolAddress((void**)&sal, g_sa_l);
    cudaGetSymbolAddress((void**)&cih, g_ci_h);
    cudaGetSymbolAddress((void**)&cil, g_ci_l);
    float *keys, *vals, *sels, *hbuf, *bkv;
    cudaGetSymbolAddress((void**)&keys, g_keys);
    cudaGetSymbolAddress((void**)&vals, g_vals);
    cudaGetSymbolAddress((void**)&sels, g_sels);
    cudaGetSymbolAddress((void**)&hbuf, g_h);
    cudaGetSymbolAddress((void**)&bkv,  g_bias_kv);
    __half *wEh, *wEl, *wSh, *wSl, *wCh, *wCl, *wKVh, *wKVl, *wQh, *wQl;
    cudaGetSymbolAddress((void**)&wEh, g_wE_h);
    cudaGetSymbolAddress((void**)&wEl, g_wE_l);
    cudaGetSymbolAddress((void**)&wSh, g_wS_h);
    cudaGetSymbolAddress((void**)&wSl, g_wS_l);
    cudaGetSymbolAddress((void**)&wCh, g_wC_h);
    cudaGetSymbolAddress((void**)&wCl, g_wC_l);
    cudaGetSymbolAddress((void**)&wKVh, g_wKV_h);
    cudaGetSymbolAddress((void**)&wKVl, g_wKV_l);
    cudaGetSymbolAddress((void**)&wQh, g_wQ_h);
    cudaGetSymbolAddress((void**)&wQl, g_wQ_l);

    cudaFuncSetAttribute(gemmH, cudaFuncAttributeMaxDynamicSharedMemorySize, SMEM_TOT);

    // ---- prep ---------------------------------------------------------------
    {
        long tX = (long)NA * NB * KP_IN;
        prep_x<<<(unsigned)((tX + 255) / 256), 256>>>(states, actions, xh, xl);
        long tE = (long)NA * 256 * KP_IN;
        prep_w<<<(unsigned)((tE + 255) / 256), 256>>>(enc_W, wEh, wEl, NIDIM, KP_IN, tE);
        prep_w<<<(unsigned)((tE + 255) / 256), 256>>>(s_W,   wSh, wSl, NS,    KP_IN, tE);
        long tC = (long)NA * 256 * KP_C;
        prep_w<<<(unsigned)((tC + 255) / 256), 256>>>(c_W1,  wCh, wCl, KP_C,  KP_C,  tC);
        prep_h<<<256, 256>>>(key_W, wKVh, wKVl);
        prep_h<<<256, 256>>>(val_W, wKVh + (size_t)256 * 256, wKVl + (size_t)256 * 256);
        prep_h<<<256, 256>>>(sel_W, wQh, wQl);
        prep_bkv<<<1, 512>>>(val_b, bkv);
    }

    dim3 blk(256);
    dim3 grd2(2, NB / 128, NA);
    dim3 grd4(4, NB / 128, NA);

    // 1) sa_enc (half-pair out)
    gemmH<<<grd2, blk, SMEM_TOT>>>(xh, xl, KP_IN, KP_IN, wEh, wEl,
        (long)256 * KP_IN, enc_b, NH, 1, nullptr, nullptr, sah, sal, NH);

    // 2) s_enc -> ci cols [0,256)
    gemmH<<<grd2, blk, SMEM_TOT>>>(xh, xl, KP_IN, KP_IN, wSh, wSl,
        (long)256 * KP_IN, s_b, NH, 1, nullptr, nullptr, cih, cil, KP_C);

    // 3) keys & vals fused (N=512; cols<256 -> keys, >=256 -> vals w/ lrelu+bias)
    gemmH<<<grd4, blk, SMEM_TOT>>>(sah, sal, NH, KP_H, wKVh, wKVl,
        0, bkv, 0, 2, keys, vals, nullptr, nullptr, 0);

    // 4) sels (A = s_enc inside ci, row stride 512)
    gemmH<<<grd2, blk, SMEM_TOT>>>(cih, cil, KP_C, KP_H, wQh, wQl,
        0, nullptr, 0, 0, sels, nullptr, nullptr, nullptr, 0);

    // 5) attention -> ci cols [256,512)
    attn_k<<<NB, 256>>>(keys, sels, vals, cih, cil);

    // 6) h = lrelu(ci @ c_W1 + c_b1)
    gemmH<<<grd2, blk, SMEM_TOT>>>(cih, cil, KP_C, KP_C, wCh, wCl,
        (long)256 * KP_C, c_b1, NH, 1, hbuf, nullptr, nullptr, nullptr, 0);

    // 7) q
    q_k<<<(NA * NB * 32) / 256, 256>>>(hbuf, actions, c_W2, c_b2, q);
}